// round 1
// baseline (speedup 1.0000x reference)
#include <cuda_runtime.h>
#include <cuda_bf16.h>
#include <math.h>

#define NN   200000
#define EE   300000
#define BB   64
#define HID  128
#define NHEAD 4
#define DH   32
#define NREL 3
#define TED  64
#define TASK 384
#define INV_SQRT_D 0.17677669529663687f

// ---------------- scratch (static device memory; no allocs allowed) ----------
__device__ float g_h[NN * HID];            // node features (in-place updated per layer)
__device__ float g_kqv[NN * 3 * HID];      // k | q | v per node
__device__ float g_kt[NREL][NN * HID];     // per-relation transformed keys
__device__ float g_vt[NREL][NN * HID];     // per-relation transformed values
__device__ float g_sc[NREL * EE * NHEAD];  // scores -> exp(scores)
__device__ float g_mx[NN * NHEAD];         // segment max
__device__ float g_sm[NN * NHEAD];         // segment sum
__device__ float g_agg[NN * HID];          // attention-weighted aggregate
__device__ float g_pool[2 * BB * HID];     // masked pools (w, 1-w)
__device__ float g_cnt[2 * BB];            // pool counts
__device__ float g_ge[BB * 256];           // graph embedding after Wtf

// ---------------- helpers ----------------------------------------------------
__device__ __forceinline__ float gelu_f(float v) {
    return 0.5f * v * (1.0f + erff(v * 0.70710678118654752f));
}

__device__ __forceinline__ void atomicMaxF(float* addr, float v) {
    // sign-split trick: non-negative floats order like signed ints,
    // negative floats order inversely like unsigned ints.
    if (v >= 0.0f) atomicMax((int*)addr, __float_as_int(v));
    else           atomicMin((unsigned int*)addr, __float_as_uint(v));
}

__global__ void k_fill(float* p, float v, int n) {
    int i = blockIdx.x * blockDim.x + threadIdx.x;
    if (i < n) p[i] = v;
}

// ---------------- input embed: h = [emb[ast], x] @ Win + bin -----------------
__global__ void k_embed(const float* __restrict__ x, const int* __restrict__ ast,
                        const float* __restrict__ emb, const float* __restrict__ Win,
                        const float* __restrict__ bin) {
    __shared__ float sW[69 * 128];   // 35.3 KB
    __shared__ float sA[32][69];     //  8.8 KB
    int tid = threadIdx.x;           // 128 threads
    for (int i = tid; i < 69 * 128; i += 128) sW[i] = Win[i];
    int n0 = blockIdx.x * 32;
    for (int idx = tid; idx < 32 * 69; idx += 128) {
        int i = idx / 69, k = idx - i * 69;
        int n = n0 + i;
        float v = 0.0f;
        if (n < NN) v = (k < TED) ? emb[ast[n] * TED + k] : x[n * 5 + (k - TED)];
        sA[i][k] = v;
    }
    __syncthreads();
    int c = tid;
    float bv = bin[c];
    for (int i = 0; i < 32; i++) {
        int n = n0 + i;
        if (n >= NN) break;
        float acc = bv;
        #pragma unroll
        for (int k = 0; k < 69; k++) acc += sA[i][k] * sW[k * 128 + c];
        g_h[n * HID + c] = acc;
    }
}

// ---------------- generic GEMM: C[M,:] tile = A[M,128] @ W[128,ld] + bias ----
// block = 64 rows x 128 cols, 256 threads, per-thread 8x4 register tile.
__global__ void k_gemm128(const float* __restrict__ A, const float* __restrict__ W,
                          const float* __restrict__ bias, float* __restrict__ C,
                          int ld) {
    __shared__ float sA[32][65];
    __shared__ __align__(16) float sW[32][128];
    int tid = threadIdx.x;
    int tx = tid & 31, ty = tid >> 5;
    int row0 = blockIdx.x * 64;
    int col0 = blockIdx.y * 128;
    float acc[8][4] = {};
    for (int kk = 0; kk < 128; kk += 32) {
        for (int t = tid; t < 64 * 32; t += 256) {
            int i = t >> 5, k = t & 31;
            sA[k][i] = A[(row0 + i) * 128 + kk + k];
        }
        for (int t = tid; t < 32 * 128; t += 256) {
            int k = t >> 7, j = t & 127;
            sW[k][j] = W[(kk + k) * ld + col0 + j];
        }
        __syncthreads();
        #pragma unroll
        for (int k = 0; k < 32; k++) {
            float4 b4 = *(const float4*)&sW[k][tx * 4];
            #pragma unroll
            for (int i = 0; i < 8; i++) {
                float a = sA[k][ty * 8 + i];
                acc[i][0] += a * b4.x; acc[i][1] += a * b4.y;
                acc[i][2] += a * b4.z; acc[i][3] += a * b4.w;
            }
        }
        __syncthreads();
    }
    #pragma unroll
    for (int i = 0; i < 8; i++) {
        int row = row0 + ty * 8 + i;
        int col = col0 + tx * 4;
        float4 o;
        o.x = acc[i][0] + bias[col + 0];
        o.y = acc[i][1] + bias[col + 1];
        o.z = acc[i][2] + bias[col + 2];
        o.w = acc[i][3] + bias[col + 3];
        *(float4*)&C[row * ld + col] = o;
    }
}

// ---------------- per-relation key/value transform ---------------------------
// kt[n,h,f] = sum_d k[n,h,d] * Wk[l,r,h,d,f]   (same for v)
__global__ void k_relkv(const float* __restrict__ Wk, const float* __restrict__ Wv, int l) {
    int r = blockIdx.y;
    __shared__ float sWk[4096];
    __shared__ float sWv[4096];
    __shared__ float skv[8][2][128];
    int tid = threadIdx.x;  // 128
    const float* wk = Wk + (l * NREL + r) * 4096;
    const float* wv = Wv + (l * NREL + r) * 4096;
    for (int t = tid; t < 4096; t += 128) { sWk[t] = wk[t]; sWv[t] = wv[t]; }
    __syncthreads();
    int h = tid >> 5, f = tid & 31;
    int ntiles = NN / 8;  // exact
    for (int tile = blockIdx.x; tile < ntiles; tile += gridDim.x) {
        for (int t = tid; t < 2048; t += 128) {
            int i = t >> 8, j = t & 255;
            int n = tile * 8 + i;
            int col = (j < 128) ? j : (j + 128);  // k: [0,128), v: [256,384)
            skv[i][j >> 7][j & 127] = g_kqv[n * 384 + col];
        }
        __syncthreads();
        #pragma unroll
        for (int i = 0; i < 8; i++) {
            float ak = 0.0f, av = 0.0f;
            const float* kk = &skv[i][0][h * 32];
            const float* vv = &skv[i][1][h * 32];
            #pragma unroll
            for (int d = 0; d < 32; d++) {
                ak += kk[d] * sWk[(h * 32 + d) * 32 + f];
                av += vv[d] * sWv[(h * 32 + d) * 32 + f];
            }
            int n = tile * 8 + i;
            g_kt[r][n * 128 + h * 32 + f] = ak;
            g_vt[r][n * 128 + h * 32 + f] = av;
        }
        __syncthreads();
    }
}

// ---------------- edge scores + segment max ----------------------------------
__global__ void k_score(const int* __restrict__ ei, const float* __restrict__ prel, int r) {
    int gw = (blockIdx.x * blockDim.x + threadIdx.x) >> 5;
    int lane = threadIdx.x & 31;
    if (gw >= EE) return;
    int src = ei[gw], dst = ei[EE + gw];
    float4 q4 = *(const float4*)(g_kqv + dst * 384 + 128 + lane * 4);
    float4 k4 = *(const float4*)(&g_kt[r][src * 128 + lane * 4]);
    float p = q4.x * k4.x + q4.y * k4.y + q4.z * k4.z + q4.w * k4.w;
    p += __shfl_down_sync(0xffffffffu, p, 4);
    p += __shfl_down_sync(0xffffffffu, p, 2);
    p += __shfl_down_sync(0xffffffffu, p, 1);
    if ((lane & 7) == 0) {
        int h = lane >> 3;
        float s = p * prel[h] * INV_SQRT_D;
        g_sc[(r * EE + gw) * 4 + h] = s;
        atomicMaxF(&g_mx[dst * 4 + h], s);
    }
}

// ---------------- exp + segment sum ------------------------------------------
__global__ void k_expsum(const int* __restrict__ e0, const int* __restrict__ e1,
                         const int* __restrict__ e2) {
    int g = blockIdx.x * blockDim.x + threadIdx.x;
    if (g >= NREL * EE * 4) return;
    int h = g & 3;
    int t = g >> 2;
    int r = t / EE;
    int e = t - r * EE;
    const int* ei = (r == 0) ? e0 : ((r == 1) ? e1 : e2);
    int dst = ei[EE + e];
    float s = g_sc[g];
    float ev = expf(s - g_mx[dst * 4 + h]);
    g_sc[g] = ev;
    atomicAdd(&g_sm[dst * 4 + h], ev);
}

// ---------------- weighted aggregation ---------------------------------------
__global__ void k_agg(const int* __restrict__ ei, int r) {
    int gw = (blockIdx.x * blockDim.x + threadIdx.x) >> 5;
    int lane = threadIdx.x & 31;
    if (gw >= EE) return;
    int src = ei[gw], dst = ei[EE + gw];
    int h = lane >> 3;
    float a = g_sc[(r * EE + gw) * 4 + h] / (g_sm[dst * 4 + h] + 1e-16f);
    float4 v4 = *(const float4*)(&g_vt[r][src * 128 + lane * 4]);
#if __CUDA_ARCH__ >= 900
    float4 o = make_float4(a * v4.x, a * v4.y, a * v4.z, a * v4.w);
    atomicAdd(reinterpret_cast<float4*>(g_agg + dst * 128 + lane * 4), o);
#else
    float* out = g_agg + dst * 128 + lane * 4;
    atomicAdd(out + 0, a * v4.x);
    atomicAdd(out + 1, a * v4.y);
    atomicAdd(out + 2, a * v4.z);
    atomicAdd(out + 3, a * v4.w);
#endif
}

// ---------------- Wout GEMM with gelu(A), skip gate, LayerNorm epilogue ------
__global__ void k_wout_ln(const float* __restrict__ W, const float* __restrict__ bout,
                          const float* __restrict__ skip, int l,
                          const float* __restrict__ ln_g, const float* __restrict__ ln_b) {
    __shared__ float sA[32][65];
    __shared__ __align__(16) float sW[32][128];
    int tid = threadIdx.x;
    int tx = tid & 31, ty = tid >> 5;
    int row0 = blockIdx.x * 64;
    float acc[8][4] = {};
    for (int kk = 0; kk < 128; kk += 32) {
        for (int t = tid; t < 64 * 32; t += 256) {
            int i = t >> 5, k = t & 31;
            sA[k][i] = gelu_f(g_agg[(row0 + i) * 128 + kk + k]);
        }
        for (int t = tid; t < 32 * 128; t += 256) {
            int k = t >> 7, j = t & 127;
            sW[k][j] = W[(kk + k) * 128 + j];
        }
        __syncthreads();
        #pragma unroll
        for (int k = 0; k < 32; k++) {
            float4 b4 = *(const float4*)&sW[k][tx * 4];
            #pragma unroll
            for (int i = 0; i < 8; i++) {
                float a = sA[k][ty * 8 + i];
                acc[i][0] += a * b4.x; acc[i][1] += a * b4.y;
                acc[i][2] += a * b4.z; acc[i][3] += a * b4.w;
            }
        }
        __syncthreads();
    }
    float alpha = 1.0f / (1.0f + expf(-skip[l]));
    float val[8][4];
    #pragma unroll
    for (int i = 0; i < 8; i++) {
        int row = row0 + ty * 8 + i;
        float rsum = 0.0f, rsq = 0.0f;
        #pragma unroll
        for (int j = 0; j < 4; j++) {
            int col = tx * 4 + j;
            float v = acc[i][j] + bout[col];
            v = alpha * v + (1.0f - alpha) * g_h[row * 128 + col];
            val[i][j] = v;
            rsum += v; rsq += v * v;
        }
        #pragma unroll
        for (int off = 16; off > 0; off >>= 1) {
            rsum += __shfl_xor_sync(0xffffffffu, rsum, off);
            rsq  += __shfl_xor_sync(0xffffffffu, rsq,  off);
        }
        float mu = rsum * (1.0f / 128.0f);
        float var = rsq * (1.0f / 128.0f) - mu * mu;
        float rstd = rsqrtf(var + 1e-5f);
        #pragma unroll
        for (int j = 0; j < 4; j++) {
            int col = tx * 4 + j;
            g_h[row * 128 + col] = (val[i][j] - mu) * rstd * ln_g[col] + ln_b[col];
        }
    }
}

// ---------------- masked mean pool (batch is sorted) -------------------------
__global__ void k_pool(const float* __restrict__ x, const int* __restrict__ batch) {
    int c = threadIdx.x;  // 128
    int n0 = blockIdx.x * 512;
    int n1 = min(n0 + 512, NN);
    if (n0 >= NN) return;
    int curb = batch[n0];
    float a1 = 0.0f, a0 = 0.0f, c1 = 0.0f, c0 = 0.0f;
    for (int n = n0; n < n1; n++) {
        int b = batch[n];
        if (b != curb) {
            atomicAdd(&g_pool[curb * 128 + c], a1);
            atomicAdd(&g_pool[BB * 128 + curb * 128 + c], a0);
            if (c == 0) { atomicAdd(&g_cnt[curb], c1); atomicAdd(&g_cnt[BB + curb], c0); }
            a1 = a0 = c1 = c0 = 0.0f;
            curb = b;
        }
        float w = (x[n * 5 + 1] > 0.0f) ? 1.0f : 0.0f;
        float hv = g_h[n * 128 + c];
        a1 += w * hv;
        a0 += (1.0f - w) * hv;
        if (c == 0) { c1 += w; c0 += 1.0f - w; }
    }
    atomicAdd(&g_pool[curb * 128 + c], a1);
    atomicAdd(&g_pool[BB * 128 + curb * 128 + c], a0);
    if (c == 0) { atomicAdd(&g_cnt[curb], c1); atomicAdd(&g_cnt[BB + curb], c0); }
}

// ---------------- task fusion: relu([ge, task] @ Wtf + btf) ------------------
__global__ void k_tf(const float* __restrict__ task, const float* __restrict__ Wtf,
                     const float* __restrict__ btf) {
    int b = blockIdx.x;
    int j = threadIdx.x;  // 256
    __shared__ float sin_[640];
    if (j < 128) {
        float c1 = g_cnt[b];
        sin_[j] = (c1 > 0.0f) ? g_pool[b * 128 + j] / c1 : 0.0f;
    } else {
        float c0 = g_cnt[BB + b];
        sin_[j] = (c0 > 0.0f) ? g_pool[BB * 128 + b * 128 + (j - 128)] / c0 : 0.0f;
    }
    for (int t = j; t < TASK; t += 256) sin_[256 + t] = task[b * TASK + t];
    __syncthreads();
    float acc = btf[j];
    for (int k = 0; k < 640; k++) acc += sin_[k] * Wtf[k * 256 + j];
    g_ge[b * 256 + j] = fmaxf(acc, 0.0f);
}

// ---------------- classifier head --------------------------------------------
__global__ void k_head(const float* __restrict__ Wc1, const float* __restrict__ bc1,
                       const float* __restrict__ Wc2, const float* __restrict__ bc2,
                       float* __restrict__ out) {
    int b = blockIdx.x;
    int j = threadIdx.x;  // 64
    __shared__ float sge[256];
    __shared__ float red[64];
    for (int t = j; t < 256; t += 64) sge[t] = g_ge[b * 256 + t];
    __syncthreads();
    float acc = bc1[j];
    for (int k = 0; k < 256; k++) acc += sge[k] * Wc1[k * 64 + j];
    float hc = fmaxf(acc, 0.0f);
    red[j] = hc * Wc2[j];
    __syncthreads();
    for (int s = 32; s > 0; s >>= 1) {
        if (j < s) red[j] += red[j + s];
        __syncthreads();
    }
    if (j == 0) out[b] = red[0] + bc2[0];
}

// ---------------- host orchestration -----------------------------------------
extern "C" void kernel_launch(void* const* d_in, const int* in_sizes, int n_in,
                              void* d_out, int out_size) {
    const float* x      = (const float*)d_in[0];
    const int*   ast    = (const int*)  d_in[1];
    const int*   batch  = (const int*)  d_in[2];
    const int*   ei0    = (const int*)  d_in[3];
    const int*   ei1    = (const int*)  d_in[4];
    const int*   ei2    = (const int*)  d_in[5];
    const float* task   = (const float*)d_in[6];
    const float* emb    = (const float*)d_in[7];
    const float* Win    = (const float*)d_in[8];
    const float* bin    = (const float*)d_in[9];
    const float* Wkqv   = (const float*)d_in[10];
    const float* bkqv   = (const float*)d_in[11];
    const float* Wk_rel = (const float*)d_in[12];
    const float* Wv_rel = (const float*)d_in[13];
    const float* p_rel  = (const float*)d_in[14];
    const float* Wout   = (const float*)d_in[15];
    const float* bout   = (const float*)d_in[16];
    const float* skip   = (const float*)d_in[17];
    const float* ln_g   = (const float*)d_in[18];
    const float* ln_b   = (const float*)d_in[19];
    const float* Wtf    = (const float*)d_in[20];
    const float* btf    = (const float*)d_in[21];
    const float* Wc1    = (const float*)d_in[22];
    const float* bc1    = (const float*)d_in[23];
    const float* Wc2    = (const float*)d_in[24];
    const float* bc2    = (const float*)d_in[25];

    float *ph, *pkqv, *pagg, *pmx, *psm, *ppool, *pcnt;
    cudaGetSymbolAddress((void**)&ph,    g_h);
    cudaGetSymbolAddress((void**)&pkqv,  g_kqv);
    cudaGetSymbolAddress((void**)&pagg,  g_agg);
    cudaGetSymbolAddress((void**)&pmx,   g_mx);
    cudaGetSymbolAddress((void**)&psm,   g_sm);
    cudaGetSymbolAddress((void**)&ppool, g_pool);
    cudaGetSymbolAddress((void**)&pcnt,  g_cnt);

    const int* eis[3] = {ei0, ei1, ei2};

    k_embed<<<(NN + 31) / 32, 128>>>(x, ast, emb, Win, bin);

    for (int l = 0; l < 2; l++) {
        // kqv = h @ Wkqv[l] + bkqv[l]   ([N,128] x [128,384])
        k_gemm128<<<dim3(NN / 64, 3), 256>>>(ph, Wkqv + l * HID * 3 * HID,
                                             bkqv + l * 3 * HID, pkqv, 384);
        // per-relation k/v transforms
        k_relkv<<<dim3(1184, NREL), 128>>>(Wk_rel, Wv_rel, l);
        // reset softmax accumulators
        k_fill<<<(NN * 4 + 255) / 256, 256>>>(pmx, -INFINITY, NN * 4);
        k_fill<<<(NN * 4 + 255) / 256, 256>>>(psm, 0.0f, NN * 4);
        k_fill<<<(NN * HID + 255) / 256, 256>>>(pagg, 0.0f, NN * HID);
        // scores + segment max
        for (int r = 0; r < NREL; r++)
            k_score<<<EE / 8, 256>>>(eis[r], p_rel + (l * NREL + r) * NHEAD, r);
        // exp + segment sum (all relations)
        k_expsum<<<(NREL * EE * 4 + 255) / 256, 256>>>(ei0, ei1, ei2);
        // weighted aggregation
        for (int r = 0; r < NREL; r++)
            k_agg<<<EE / 8, 256>>>(eis[r], r);
        // out = LN(alpha*(gelu(agg)@Wout+bout) + (1-alpha)*h), in place on g_h
        k_wout_ln<<<NN / 64, 256>>>(Wout + l * HID * HID, bout + l * HID,
                                    skip, l, ln_g + l * HID, ln_b + l * HID);
    }

    // pooling + head
    k_fill<<<(2 * BB * HID + 255) / 256, 256>>>(ppool, 0.0f, 2 * BB * HID);
    k_fill<<<1, 256>>>(pcnt, 0.0f, 2 * BB);
    k_pool<<<(NN + 511) / 512, 128>>>(x, batch);
    k_tf<<<BB, 256>>>(task, Wtf, btf);
    k_head<<<BB, 64>>>(Wc1, bc1, Wc2, bc2, (float*)d_out);
}

// round 2
// speedup vs baseline: 1.2812x; 1.2812x over previous
#include <cuda_runtime.h>
#include <cuda_bf16.h>
#include <math.h>

#define NN   200000
#define EE   300000
#define BB   64
#define HID  128
#define NHEAD 4
#define NREL 3
#define TED  64
#define TASK 384
#define INV_SQRT_D 0.17677669529663687f

// ---------------- scratch ----------------------------------------------------
__device__ float g_h[NN * HID];
__device__ float g_kqv[NN * 3 * HID];
__device__ float g_kt[NREL][NN * HID];
__device__ float g_vt[NREL][NN * HID];
__device__ float g_agg[NN * HID];
__device__ int   g_deg[NN];
__device__ int   g_off[NN + 1];
__device__ int   g_cur[NN];
__device__ int   g_edge[NREL * EE];     // src | (rel<<18)
__device__ float g_pool[2 * BB * HID];
__device__ float g_cnt[2 * BB];
__device__ float g_ge[BB * 256];

// ---------------- helpers ----------------------------------------------------
__device__ __forceinline__ float gelu_f(float v) {
    return 0.5f * v * (1.0f + erff(v * 0.70710678118654752f));
}

#define PACK2(d, s)  asm("mov.b64 %0, {%1, %1};" : "=l"(d) : "f"(s))
#define UNPK2(lo, hi, s) asm("mov.b64 {%0, %1}, %2;" : "=f"(lo), "=f"(hi) : "l"(s))
#define FFMA2(c_, a_, b_) \
    asm("fma.rn.f32x2 %0, %1, %2, %3;" : "=l"(c_) : "l"(a_), "l"(b_), "l"(c_))

__global__ void k_fill(float* p, float v, int n) {
    int i = blockIdx.x * blockDim.x + threadIdx.x;
    if (i < n) p[i] = v;
}
__global__ void k_filli(int* p, int v, int n) {
    int i = blockIdx.x * blockDim.x + threadIdx.x;
    if (i < n) p[i] = v;
}

// ---------------- CSR build ---------------------------------------------------
__global__ void k_hist(const int* __restrict__ e0, const int* __restrict__ e1,
                       const int* __restrict__ e2) {
    int g = blockIdx.x * blockDim.x + threadIdx.x;
    if (g >= NREL * EE) return;
    int r = g / EE, e = g - r * EE;
    const int* ei = (r == 0) ? e0 : ((r == 1) ? e1 : e2);
    atomicAdd(&g_deg[ei[EE + e]], 1);
}

__global__ void k_scan() {   // single block, 1024 threads
    __shared__ int part[1024];
    int tid = threadIdx.x;
    const int CH = (NN + 1023) / 1024;
    int b0 = tid * CH, b1 = min(b0 + CH, NN);
    int s = 0;
    for (int i = b0; i < b1; i++) s += g_deg[i];
    part[tid] = s;
    __syncthreads();
    for (int off = 1; off < 1024; off <<= 1) {
        int v = (tid >= off) ? part[tid - off] : 0;
        __syncthreads();
        part[tid] += v;
        __syncthreads();
    }
    int run = (tid > 0) ? part[tid - 1] : 0;
    for (int i = b0; i < b1; i++) {
        int d = g_deg[i];
        g_off[i] = run;
        g_cur[i] = run;
        run += d;
    }
    if (tid == 1023) g_off[NN] = run;
}

__global__ void k_scatter(const int* __restrict__ e0, const int* __restrict__ e1,
                          const int* __restrict__ e2) {
    int g = blockIdx.x * blockDim.x + threadIdx.x;
    if (g >= NREL * EE) return;
    int r = g / EE, e = g - r * EE;
    const int* ei = (r == 0) ? e0 : ((r == 1) ? e1 : e2);
    int src = ei[e], dst = ei[EE + e];
    int pos = atomicAdd(&g_cur[dst], 1);
    g_edge[pos] = src | (r << 18);
}

// ---------------- input embed ------------------------------------------------
__global__ void k_embed(const float* __restrict__ x, const int* __restrict__ ast,
                        const float* __restrict__ emb, const float* __restrict__ Win,
                        const float* __restrict__ bin) {
    __shared__ float sW[69 * 128];
    __shared__ float sA[32][69];
    int tid = threadIdx.x;   // 128
    for (int i = tid; i < 69 * 128; i += 128) sW[i] = Win[i];
    int n0 = blockIdx.x * 32;
    for (int idx = tid; idx < 32 * 69; idx += 128) {
        int i = idx / 69, k = idx - i * 69;
        int n = n0 + i;
        float v = 0.0f;
        if (n < NN) v = (k < TED) ? emb[ast[n] * TED + k] : x[n * 5 + (k - TED)];
        sA[i][k] = v;
    }
    __syncthreads();
    int c = tid;
    float bv = bin[c];
    for (int i = 0; i < 32; i++) {
        int n = n0 + i;
        if (n >= NN) break;
        float acc = bv;
        #pragma unroll
        for (int k = 0; k < 69; k++) acc += sA[i][k] * sW[k * 128 + c];
        g_h[n * HID + c] = acc;
    }
}

// ---------------- kqv GEMM: [N,128] x [128,384], 128x128 tiles, FFMA2 --------
__global__ __launch_bounds__(256, 2)
void k_gemm_kqv(const float* __restrict__ A, const float* __restrict__ W,
                const float* __restrict__ bias, float* __restrict__ C) {
    __shared__ float sA[16][132];
    __shared__ __align__(16) float sW[16][128];
    int tid = threadIdx.x, tx = tid & 15, ty = tid >> 4;
    int row0 = blockIdx.x * 128, col0 = blockIdx.y * 128;
    unsigned long long acc[8][4];
    #pragma unroll
    for (int i = 0; i < 8; i++)
        #pragma unroll
        for (int j = 0; j < 4; j++) acc[i][j] = 0ULL;

    for (int kk = 0; kk < 128; kk += 16) {
        #pragma unroll
        for (int t = 0; t < 2; t++) {
            int f = tid + t * 256;
            int r = f >> 2, c = f & 3;
            int row = row0 + r; if (row >= NN) row = NN - 1;
            float4 a4 = *(const float4*)&A[row * 128 + kk + c * 4];
            sA[c * 4 + 0][r] = a4.x; sA[c * 4 + 1][r] = a4.y;
            sA[c * 4 + 2][r] = a4.z; sA[c * 4 + 3][r] = a4.w;
        }
        #pragma unroll
        for (int t = 0; t < 2; t++) {
            int f = tid + t * 256;
            int r = f >> 5, c = f & 31;
            *(float4*)&sW[r][c * 4] = *(const float4*)&W[(kk + r) * 384 + col0 + c * 4];
        }
        __syncthreads();
        #pragma unroll
        for (int k = 0; k < 16; k++) {
            float4 a0 = *(const float4*)&sA[k][ty * 8];
            float4 a1 = *(const float4*)&sA[k][ty * 8 + 4];
            ulonglong2 b0 = *(const ulonglong2*)&sW[k][tx * 8];
            ulonglong2 b1 = *(const ulonglong2*)&sW[k][tx * 8 + 4];
            unsigned long long av[8];
            PACK2(av[0], a0.x); PACK2(av[1], a0.y); PACK2(av[2], a0.z); PACK2(av[3], a0.w);
            PACK2(av[4], a1.x); PACK2(av[5], a1.y); PACK2(av[6], a1.z); PACK2(av[7], a1.w);
            #pragma unroll
            for (int i = 0; i < 8; i++) {
                FFMA2(acc[i][0], av[i], b0.x);
                FFMA2(acc[i][1], av[i], b0.y);
                FFMA2(acc[i][2], av[i], b1.x);
                FFMA2(acc[i][3], av[i], b1.y);
            }
        }
        __syncthreads();
    }
    int colb = col0 + tx * 8;
    float bsv[8];
    #pragma unroll
    for (int j = 0; j < 8; j++) bsv[j] = bias[colb + j];
    #pragma unroll
    for (int i = 0; i < 8; i++) {
        int row = row0 + ty * 8 + i;
        if (row >= NN) continue;
        float v[8];
        #pragma unroll
        for (int j = 0; j < 4; j++) UNPK2(v[2 * j], v[2 * j + 1], acc[i][j]);
        float4 o0 = make_float4(v[0] + bsv[0], v[1] + bsv[1], v[2] + bsv[2], v[3] + bsv[3]);
        float4 o1 = make_float4(v[4] + bsv[4], v[5] + bsv[5], v[6] + bsv[6], v[7] + bsv[7]);
        *(float4*)&C[row * 384 + colb] = o0;
        *(float4*)&C[row * 384 + colb + 4] = o1;
    }
}

// ---------------- per-relation k/v transform (register weights) --------------
__global__ __launch_bounds__(256, 4)
void k_relkv(const float* __restrict__ Wk, const float* __restrict__ Wv, int l) {
    __shared__ float sT[32][256];   // 32 nodes x (k 128 | v 128)
    int r = blockIdx.y;
    int tid = threadIdx.x;
    int w = tid >> 5, lane = tid & 31;
    int kv = w & 1, h = w >> 1;
    const float* wbase = ((kv == 0) ? Wk : Wv) + (l * NREL + r) * 4096 + h * 1024 + lane;
    float wr[32];
    #pragma unroll
    for (int d = 0; d < 32; d++) wr[d] = wbase[d * 32];

    int n0 = blockIdx.x * 32;
    #pragma unroll
    for (int t = 0; t < 8; t++) {
        int f = tid + t * 256;           // 2048 float4s
        int i = f >> 6, c = f & 63;
        int col = (c < 32) ? c * 4 : 256 + (c - 32) * 4;
        *(float4*)&sT[i][(c < 32) ? c * 4 : 128 + (c - 32) * 4] =
            *(const float4*)&g_kqv[(n0 + i) * 384 + col];
    }
    __syncthreads();
    float* outb = (kv == 0) ? g_kt[r] : g_vt[r];
    for (int i = 0; i < 32; i++) {
        const float* base = &sT[i][kv * 128 + h * 32];
        float acc = 0.0f;
        #pragma unroll
        for (int t = 0; t < 8; t++) {
            float4 a = *(const float4*)(base + 4 * t);
            acc += a.x * wr[4 * t] + a.y * wr[4 * t + 1] + a.z * wr[4 * t + 2] + a.w * wr[4 * t + 3];
        }
        outb[(n0 + i) * 128 + h * 32 + lane] = acc;
    }
}

// ---------------- fused edge attention: online softmax, warp per dst ---------
__global__ __launch_bounds__(256)
void k_edge(const float* __restrict__ prel) {
    int gw = (blockIdx.x * blockDim.x + threadIdx.x) >> 5;
    if (gw >= NN) return;
    int lane = threadIdx.x & 31;
    int h = lane >> 3;
    float p0 = prel[h] * INV_SQRT_D;
    float p1 = prel[4 + h] * INV_SQRT_D;
    float p2 = prel[8 + h] * INV_SQRT_D;
    float4 q4 = *(const float4*)&g_kqv[gw * 384 + 128 + lane * 4];
    int e0 = g_off[gw], e1 = g_off[gw + 1];
    float m = -INFINITY, z = 0.0f;
    float4 acc = make_float4(0.f, 0.f, 0.f, 0.f);
    for (int e = e0; e < e1; e++) {
        int pk = g_edge[e];
        int src = pk & 0x3FFFF;
        int r = pk >> 18;
        const float* ktb = &g_kt[r][src * 128 + lane * 4];
        float4 k4 = *(const float4*)ktb;
        float s = q4.x * k4.x + q4.y * k4.y + q4.z * k4.z + q4.w * k4.w;
        s += __shfl_xor_sync(0xffffffffu, s, 1);
        s += __shfl_xor_sync(0xffffffffu, s, 2);
        s += __shfl_xor_sync(0xffffffffu, s, 4);
        s *= (r == 0) ? p0 : ((r == 1) ? p1 : p2);
        float mn = fmaxf(m, s);
        float es = expf(s - mn);
        float corr = expf(m - mn);   // m=-inf first iter -> 0
        z = z * corr + es;
        float4 v4 = *(const float4*)&g_vt[r][src * 128 + lane * 4];
        acc.x = acc.x * corr + es * v4.x;
        acc.y = acc.y * corr + es * v4.y;
        acc.z = acc.z * corr + es * v4.z;
        acc.w = acc.w * corr + es * v4.w;
        m = mn;
    }
    float inv = 1.0f / (z + 1e-16f);
    *(float4*)&g_agg[gw * 128 + lane * 4] =
        make_float4(acc.x * inv, acc.y * inv, acc.z * inv, acc.w * inv);
}

// ---------------- Wout GEMM (gelu A) + skip + LayerNorm, FFMA2 ---------------
__global__ __launch_bounds__(256, 2)
void k_wout_ln(const float* __restrict__ W, const float* __restrict__ bout,
               const float* __restrict__ skip, int l,
               const float* __restrict__ ln_g, const float* __restrict__ ln_b) {
    __shared__ float sA[16][132];
    __shared__ __align__(16) float sW[16][128];
    int tid = threadIdx.x, tx = tid & 15, ty = tid >> 4;
    int row0 = blockIdx.x * 128;
    unsigned long long acc[8][4];
    #pragma unroll
    for (int i = 0; i < 8; i++)
        #pragma unroll
        for (int j = 0; j < 4; j++) acc[i][j] = 0ULL;

    for (int kk = 0; kk < 128; kk += 16) {
        #pragma unroll
        for (int t = 0; t < 2; t++) {
            int f = tid + t * 256;
            int r = f >> 2, c = f & 3;
            int row = row0 + r; if (row >= NN) row = NN - 1;
            float4 a4 = *(const float4*)&g_agg[row * 128 + kk + c * 4];
            sA[c * 4 + 0][r] = gelu_f(a4.x); sA[c * 4 + 1][r] = gelu_f(a4.y);
            sA[c * 4 + 2][r] = gelu_f(a4.z); sA[c * 4 + 3][r] = gelu_f(a4.w);
        }
        #pragma unroll
        for (int t = 0; t < 2; t++) {
            int f = tid + t * 256;
            int r = f >> 5, c = f & 31;
            *(float4*)&sW[r][c * 4] = *(const float4*)&W[(kk + r) * 128 + c * 4];
        }
        __syncthreads();
        #pragma unroll
        for (int k = 0; k < 16; k++) {
            float4 a0 = *(const float4*)&sA[k][ty * 8];
            float4 a1 = *(const float4*)&sA[k][ty * 8 + 4];
            ulonglong2 b0 = *(const ulonglong2*)&sW[k][tx * 8];
            ulonglong2 b1 = *(const ulonglong2*)&sW[k][tx * 8 + 4];
            unsigned long long av[8];
            PACK2(av[0], a0.x); PACK2(av[1], a0.y); PACK2(av[2], a0.z); PACK2(av[3], a0.w);
            PACK2(av[4], a1.x); PACK2(av[5], a1.y); PACK2(av[6], a1.z); PACK2(av[7], a1.w);
            #pragma unroll
            for (int i = 0; i < 8; i++) {
                FFMA2(acc[i][0], av[i], b0.x);
                FFMA2(acc[i][1], av[i], b0.y);
                FFMA2(acc[i][2], av[i], b1.x);
                FFMA2(acc[i][3], av[i], b1.y);
            }
        }
        __syncthreads();
    }
    float alpha = 1.0f / (1.0f + expf(-skip[l]));
    int colb = tx * 8;
    float bsv[8], gv[8], bv[8];
    #pragma unroll
    for (int j = 0; j < 8; j++) {
        bsv[j] = bout[colb + j];
        gv[j] = ln_g[colb + j];
        bv[j] = ln_b[colb + j];
    }
    #pragma unroll
    for (int i = 0; i < 8; i++) {
        int row = row0 + ty * 8 + i;
        if (row >= NN) continue;
        float v[8];
        #pragma unroll
        for (int j = 0; j < 4; j++) UNPK2(v[2 * j], v[2 * j + 1], acc[i][j]);
        float4 h0 = *(const float4*)&g_h[row * 128 + colb];
        float4 h1 = *(const float4*)&g_h[row * 128 + colb + 4];
        float hv[8] = {h0.x, h0.y, h0.z, h0.w, h1.x, h1.y, h1.z, h1.w};
        float rsum = 0.0f, rsq = 0.0f;
        #pragma unroll
        for (int j = 0; j < 8; j++) {
            float t = alpha * (v[j] + bsv[j]) + (1.0f - alpha) * hv[j];
            v[j] = t;
            rsum += t; rsq += t * t;
        }
        #pragma unroll
        for (int off = 8; off > 0; off >>= 1) {   // reduce over 16 lanes (same ty)
            rsum += __shfl_xor_sync(0xffffffffu, rsum, off);
            rsq  += __shfl_xor_sync(0xffffffffu, rsq,  off);
        }
        float mu = rsum * (1.0f / 128.0f);
        float var = rsq * (1.0f / 128.0f) - mu * mu;
        float rstd = rsqrtf(var + 1e-5f);
        float4 o0, o1;
        o0.x = (v[0] - mu) * rstd * gv[0] + bv[0];
        o0.y = (v[1] - mu) * rstd * gv[1] + bv[1];
        o0.z = (v[2] - mu) * rstd * gv[2] + bv[2];
        o0.w = (v[3] - mu) * rstd * gv[3] + bv[3];
        o1.x = (v[4] - mu) * rstd * gv[4] + bv[4];
        o1.y = (v[5] - mu) * rstd * gv[5] + bv[5];
        o1.z = (v[6] - mu) * rstd * gv[6] + bv[6];
        o1.w = (v[7] - mu) * rstd * gv[7] + bv[7];
        *(float4*)&g_h[row * 128 + colb] = o0;
        *(float4*)&g_h[row * 128 + colb + 4] = o1;
    }
}

// ---------------- masked mean pool (batch sorted) ----------------------------
__global__ void k_pool(const float* __restrict__ x, const int* __restrict__ batch) {
    int c = threadIdx.x;  // 128
    int n0 = blockIdx.x * 512;
    int n1 = min(n0 + 512, NN);
    if (n0 >= NN) return;
    int curb = batch[n0];
    float a1 = 0.0f, a0 = 0.0f, c1 = 0.0f, c0 = 0.0f;
    for (int n = n0; n < n1; n++) {
        int b = batch[n];
        if (b != curb) {
            atomicAdd(&g_pool[curb * 128 + c], a1);
            atomicAdd(&g_pool[BB * 128 + curb * 128 + c], a0);
            if (c == 0) { atomicAdd(&g_cnt[curb], c1); atomicAdd(&g_cnt[BB + curb], c0); }
            a1 = a0 = c1 = c0 = 0.0f;
            curb = b;
        }
        float w = (x[n * 5 + 1] > 0.0f) ? 1.0f : 0.0f;
        float hv = g_h[n * 128 + c];
        a1 += w * hv;
        a0 += (1.0f - w) * hv;
        if (c == 0) { c1 += w; c0 += 1.0f - w; }
    }
    atomicAdd(&g_pool[curb * 128 + c], a1);
    atomicAdd(&g_pool[BB * 128 + curb * 128 + c], a0);
    if (c == 0) { atomicAdd(&g_cnt[curb], c1); atomicAdd(&g_cnt[BB + curb], c0); }
}

// ---------------- task fusion + head -----------------------------------------
__global__ void k_tf(const float* __restrict__ task, const float* __restrict__ Wtf,
                     const float* __restrict__ btf) {
    int b = blockIdx.x;
    int j = threadIdx.x;  // 256
    __shared__ float sin_[640];
    if (j < 128) {
        float c1 = g_cnt[b];
        sin_[j] = (c1 > 0.0f) ? g_pool[b * 128 + j] / c1 : 0.0f;
    } else {
        float c0 = g_cnt[BB + b];
        sin_[j] = (c0 > 0.0f) ? g_pool[BB * 128 + b * 128 + (j - 128)] / c0 : 0.0f;
    }
    for (int t = j; t < TASK; t += 256) sin_[256 + t] = task[b * TASK + t];
    __syncthreads();
    float acc = btf[j];
    for (int k = 0; k < 640; k++) acc += sin_[k] * Wtf[k * 256 + j];
    g_ge[b * 256 + j] = fmaxf(acc, 0.0f);
}

__global__ void k_head(const float* __restrict__ Wc1, const float* __restrict__ bc1,
                       const float* __restrict__ Wc2, const float* __restrict__ bc2,
                       float* __restrict__ out) {
    int b = blockIdx.x;
    int j = threadIdx.x;  // 64
    __shared__ float sge[256];
    __shared__ float red[64];
    for (int t = j; t < 256; t += 64) sge[t] = g_ge[b * 256 + t];
    __syncthreads();
    float acc = bc1[j];
    for (int k = 0; k < 256; k++) acc += sge[k] * Wc1[k * 64 + j];
    float hc = fmaxf(acc, 0.0f);
    red[j] = hc * Wc2[j];
    __syncthreads();
    for (int s = 32; s > 0; s >>= 1) {
        if (j < s) red[j] += red[j + s];
        __syncthreads();
    }
    if (j == 0) out[b] = red[0] + bc2[0];
}

// ---------------- host orchestration -----------------------------------------
extern "C" void kernel_launch(void* const* d_in, const int* in_sizes, int n_in,
                              void* d_out, int out_size) {
    const float* x      = (const float*)d_in[0];
    const int*   ast    = (const int*)  d_in[1];
    const int*   batch  = (const int*)  d_in[2];
    const int*   ei0    = (const int*)  d_in[3];
    const int*   ei1    = (const int*)  d_in[4];
    const int*   ei2    = (const int*)  d_in[5];
    const float* task   = (const float*)d_in[6];
    const float* emb    = (const float*)d_in[7];
    const float* Win    = (const float*)d_in[8];
    const float* bin    = (const float*)d_in[9];
    const float* Wkqv   = (const float*)d_in[10];
    const float* bkqv   = (const float*)d_in[11];
    const float* Wk_rel = (const float*)d_in[12];
    const float* Wv_rel = (const float*)d_in[13];
    const float* p_rel  = (const float*)d_in[14];
    const float* Wout   = (const float*)d_in[15];
    const float* bout   = (const float*)d_in[16];
    const float* skip   = (const float*)d_in[17];
    const float* ln_g   = (const float*)d_in[18];
    const float* ln_b   = (const float*)d_in[19];
    const float* Wtf    = (const float*)d_in[20];
    const float* btf    = (const float*)d_in[21];
    const float* Wc1    = (const float*)d_in[22];
    const float* bc1    = (const float*)d_in[23];
    const float* Wc2    = (const float*)d_in[24];
    const float* bc2    = (const float*)d_in[25];

    float *ph, *pkqv, *ppool, *pcnt;
    int *pdeg;
    cudaGetSymbolAddress((void**)&ph,    g_h);
    cudaGetSymbolAddress((void**)&pkqv,  g_kqv);
    cudaGetSymbolAddress((void**)&ppool, g_pool);
    cudaGetSymbolAddress((void**)&pcnt,  g_cnt);
    cudaGetSymbolAddress((void**)&pdeg,  g_deg);

    // CSR build (reused for both layers)
    k_filli<<<(NN + 255) / 256, 256>>>(pdeg, 0, NN);
    k_hist<<<(NREL * EE + 255) / 256, 256>>>(ei0, ei1, ei2);
    k_scan<<<1, 1024>>>();
    k_scatter<<<(NREL * EE + 255) / 256, 256>>>(ei0, ei1, ei2);

    k_embed<<<(NN + 31) / 32, 128>>>(x, ast, emb, Win, bin);

    for (int l = 0; l < 2; l++) {
        k_gemm_kqv<<<dim3((NN + 127) / 128, 3), 256>>>(
            ph, Wkqv + l * HID * 3 * HID, bkqv + l * 3 * HID, pkqv);
        k_relkv<<<dim3(NN / 32, NREL), 256>>>(Wk_rel, Wv_rel, l);
        k_edge<<<(NN + 7) / 8, 256>>>(p_rel + l * NREL * NHEAD);
        k_wout_ln<<<(NN + 127) / 128, 256>>>(Wout + l * HID * HID, bout + l * HID,
                                             skip, l, ln_g + l * HID, ln_b + l * HID);
    }

    k_fill<<<(2 * BB * HID + 255) / 256, 256>>>(ppool, 0.0f, 2 * BB * HID);
    k_fill<<<1, 256>>>(pcnt, 0.0f, 2 * BB);
    k_pool<<<(NN + 511) / 512, 128>>>(x, batch);
    k_tf<<<BB, 256>>>(task, Wtf, btf);
    k_head<<<BB, 64>>>(Wc1, bc1, Wc2, bc2, (float*)d_out);
}